// round 13
// baseline (speedup 1.0000x reference)
#include <cuda_runtime.h>
#include <cuda_fp16.h>
#include <cstdint>

// Problem constants (fixed by the dataset)
#define PM 4
#define PK 8192
#define PKK (PK/2)            // 4096 packed-k rows
#define PN 28672
#define PG 128                // group size (k elements)
// Geometry: 256-thr CTAs, 4 CTAs/SM -> 592 slots >= 448 CTAs = ONE wave
#define THREADS 256
#define COLS_PER_THREAD 4
#define COLS_PER_CTA (THREADS*COLS_PER_THREAD)   // 1024
#define NB (PN/COLS_PER_CTA)                     // 28
#define KSPLIT 16
#define KK_PER_SPLIT (PKK/KSPLIT)                // 256
#define GROUPS_PER_SPLIT (KK_PER_SPLIT/(PG/2))   // 4
// cp.async staging (8KB chunks, 4-stage ring = 32KB)
#define RCH 2                                    // rows per chunk
#define CHUNKS (KK_PER_SPLIT/RCH)                // 128
#define CHUNKS_PER_GROUP ((PG/2)/RCH)            // 32
#define STAGES 4
// Dynamic smem layout
#define WSM_BYTES (STAGES * RCH * COLS_PER_CTA * 4)   // 32768
#define XS_BYTES  (KK_PER_SPLIT * 4 * 8)              // 8192
#define SMEM_TOTAL (WSM_BYTES + XS_BYTES)             // 40960 -> 4 CTAs/SM

// Split-K partials: [KSPLIT][M][N] fp32 (7.3MB). Static device global.
__device__ float g_scratch[KSPLIT * PM * PN];

// Packed f32x2 FMA (Blackwell, PTX-only)
__device__ __forceinline__ void fma_f32x2(unsigned long long& acc,
                                          unsigned long long a,
                                          unsigned long long b) {
    asm("fma.rn.f32x2 %0, %1, %2, %0;" : "+l"(acc) : "l"(a), "l"(b));
}
__device__ __forceinline__ unsigned long long pack_f32x2(float lo, float hi) {
    unsigned long long r;
    asm("mov.b64 %0, {%1, %2};" : "=l"(r) : "f"(lo), "f"(hi));
    return r;
}
__device__ __forceinline__ void unpack_f32x2(unsigned long long v, float& lo, float& hi) {
    asm("mov.b64 {%0, %1}, %2;" : "=f"(lo), "=f"(hi) : "l"(v));
}
__device__ __forceinline__ uint32_t smem_u32(const void* p) {
    uint32_t a;
    asm("{ .reg .u64 t; cvta.to.shared.u64 t, %1; cvt.u32.u64 %0, t; }" : "=r"(a) : "l"(p));
    return a;
}
__device__ __forceinline__ void cp_async16(uint32_t dst, const void* src) {
    asm volatile("cp.async.cg.shared.global [%0], [%1], 16;" :: "r"(dst), "l"(src) : "memory");
}
__device__ __forceinline__ void cp_commit() {
    asm volatile("cp.async.commit_group;" ::: "memory");
}
template<int N>
__device__ __forceinline__ void cp_wait() {
    asm volatile("cp.async.wait_group %0;" :: "n"(N) : "memory");
}

extern __shared__ char dynsmem[];

__global__ void __launch_bounds__(THREADS, 4)
int4gemv_main(const float* __restrict__ x,      // fp16 promoted to f32 by harness
              const int*   __restrict__ w,
              const float* __restrict__ scales) // fp16 promoted to f32 by harness
{
    // Dynamic smem: [STAGES][RCH][COLS_PER_CTA] ints, then xs2.
    int* wsm = reinterpret_cast<int*>(dynsmem);
    unsigned long long* xs2 = reinterpret_cast<unsigned long long*>(dynsmem + WSM_BYTES);

    const int tid     = threadIdx.x;
    const int nb      = blockIdx.x;
    const int ks      = blockIdx.y;
    const int kk0     = ks * KK_PER_SPLIT;
    const int colBase = nb * COLS_PER_CTA + tid * COLS_PER_THREAD;

    // Preload x slice: xs2[kk*4 + m] = (x[m][2kk], x[m][2kk+1]) via float2 loads.
    {
        float2* xsf2 = reinterpret_cast<float2*>(xs2);
        for (int i = tid; i < KK_PER_SPLIT * 4; i += THREADS) {
            const int kkl = i >> 2;
            const int m   = i & 3;
            xsf2[kkl * 4 + m] =
                *reinterpret_cast<const float2*>(x + m * PK + 2 * (kk0 + kkl));
        }
    }
    __syncthreads();   // xs2 is cross-thread; wsm is NOT (self-produced/consumed)

    // Each thread copies, for every row, the 16B it will itself consume.
    const uint32_t wsm_base = smem_u32(wsm) + (uint32_t)tid * 16u;
    const int*     wsrcBase = w + colBase;   // + row*PN per row

    // Issue one chunk (RCH rows x 16B/thread) into a stage. Out-of-range chunks
    // still commit an EMPTY group (legal) so wait_group bookkeeping stays exact.
    auto issue_chunk = [&](int chunk, int stage) {
        if (chunk < CHUNKS) {
            #pragma unroll
            for (int j = 0; j < RCH; ++j) {
                const int row = kk0 + chunk * RCH + j;   // always in-split: no overfetch
                cp_async16(wsm_base + (uint32_t)(stage * RCH + j) * (COLS_PER_CTA * 4),
                           wsrcBase + (size_t)row * PN);
            }
        }
        cp_commit();
    };

    // acc2[c][m] = (sum over even k, sum over odd k) as packed f32x2
    unsigned long long acc2[COLS_PER_THREAD][PM];
    #pragma unroll
    for (int c = 0; c < COLS_PER_THREAD; ++c)
        #pragma unroll
        for (int m = 0; m < PM; ++m) acc2[c][m] = 0ull;

    const __half2 c1032 = __half2half2(__ushort_as_half((unsigned short)0x6408)); // 1032.0h

    // Prologue: fill all 4 stages -> 3 chunks in flight during each compute.
    #pragma unroll
    for (int p = 0; p < STAGES; ++p) issue_chunk(p, p);

    __half2 s2[COLS_PER_THREAD];
    #pragma unroll 4
    for (int i = 0; i < CHUNKS; ++i) {
        const int stage = i & (STAGES - 1);

        // Refresh scales at group boundaries.
        if ((i % CHUNKS_PER_GROUP) == 0) {
            const int grow = ks * GROUPS_PER_SPLIT + (i / CHUNKS_PER_GROUP);
            float4 sv = *reinterpret_cast<const float4*>(scales + (size_t)grow * PN + colBase);
            s2[0] = __half2half2(__float2half_rn(sv.x));
            s2[1] = __half2half2(__float2half_rn(sv.y));
            s2[2] = __half2half2(__float2half_rn(sv.z));
            s2[3] = __half2half2(__float2half_rn(sv.w));
        }

        cp_wait<STAGES - 1>();   // chunk i complete; i+1..i+3 may remain in flight

        // Compute chunk i: RCH kk rows; each thread reads back its own 16B per row.
        #pragma unroll
        for (int j = 0; j < RCH; ++j) {
            const int kkl = i * RCH + j;
            const unsigned long long* xp = &xs2[kkl * 4];
            unsigned long long xm0 = xp[0];
            unsigned long long xm1 = xp[1];
            unsigned long long xm2 = xp[2];
            unsigned long long xm3 = xp[3];

            int4 wv = *reinterpret_cast<const int4*>(
                &wsm[(stage * RCH + j) * COLS_PER_CTA + tid * 4]);
            int wb[4] = {wv.x, wv.y, wv.z, wv.w};
            #pragma unroll
            for (int c = 0; c < 4; ++c) {
                // nibble -> fp16 magic: (0x6400 | nib) = 1024 + nib ; exact -1032 => nib-8
                unsigned int bb = (unsigned int)wb[c];
                unsigned int t = (((bb << 12) | bb) & 0x000F000Fu) | 0x64006400u;
                __half2 h2 = *reinterpret_cast<__half2*>(&t);
                __half2 w2 = __hsub2(h2, c1032);     // exact: (w-8) in fp16
                __half2 dq = __hmul2(w2, s2[c]);     // fp16 round == reference deq
                float d0 = __half2float(__low2half(dq));   // even k
                float d1 = __half2float(__high2half(dq));  // odd  k
                unsigned long long d64 = pack_f32x2(d0, d1);

                fma_f32x2(acc2[c][0], xm0, d64);
                fma_f32x2(acc2[c][1], xm1, d64);
                fma_f32x2(acc2[c][2], xm2, d64);
                fma_f32x2(acc2[c][3], xm3, d64);
            }
        }

        // Refill the stage we just consumed.
        issue_chunk(i + STAGES, stage);
    }

    // Collapse even/odd halves and write split partials (coalesced float4 per row).
    float* sc = g_scratch + (size_t)ks * PM * PN;
    #pragma unroll
    for (int m = 0; m < PM; ++m) {
        float r[4];
        #pragma unroll
        for (int c = 0; c < 4; ++c) {
            float lo, hi;
            unpack_f32x2(acc2[c][m], lo, hi);
            r[c] = lo + hi;
        }
        float4 v = make_float4(r[0], r[1], r[2], r[3]);
        *reinterpret_cast<float4*>(sc + m * PN + colBase) = v;
    }
}

__global__ void __launch_bounds__(256)
int4gemv_reduce(const float* __restrict__ bias,
                float* __restrict__ out)
{
    // One output element per thread: 114,688 threads,
    // 16 independent coalesced 4B loads each.
    int idx = blockIdx.x * blockDim.x + threadIdx.x;
    if (idx >= PM * PN) return;

    float s = 0.f;
    #pragma unroll
    for (int ks = 0; ks < KSPLIT; ++ks)
        s += g_scratch[ks * PM * PN + idx];

    int n = idx % PN;
    // Match reference exactly: f32 -> fp16 round, fp16 bias add, back to f32.
    __half h = __float2half_rn(s);
    __half b = __float2half_rn(bias[n]);
    out[idx] = __half2float(__hadd(h, b));
}

extern "C" void kernel_launch(void* const* d_in, const int* in_sizes, int n_in,
                              void* d_out, int out_size)
{
    // Bind inputs BY ELEMENT COUNT (dtype-invariant, robust to ordering):
    //   x: 32768, weight_packed: 117440512, scales: 1835008, bias: 28672
    const float* x      = nullptr;
    const int*   w      = nullptr;
    const float* scales = nullptr;
    const float* bias   = nullptr;

    for (int i = 0; i < n_in; ++i) {
        switch (in_sizes[i]) {
            case PM * PK:        x      = (const float*)d_in[i]; break;
            case PKK * PN:       w      = (const int*)  d_in[i]; break;
            case (PK/PG) * PN:   scales = (const float*)d_in[i]; break;
            case PN:             bias   = (const float*)d_in[i]; break;
            default: break; // group_size scalar etc.
        }
    }

    float* out = (float*)d_out;

    // Host-side attribute set (not a stream op; capture-safe, idempotent).
    static bool attr_done = false;
    if (!attr_done) {
        cudaFuncSetAttribute(int4gemv_main,
                             cudaFuncAttributeMaxDynamicSharedMemorySize, SMEM_TOTAL);
        attr_done = true;
    }

    dim3 grid(NB, KSPLIT);
    int4gemv_main<<<grid, THREADS, SMEM_TOTAL>>>(x, w, scales);

    int tot = PM * PN;
    int4gemv_reduce<<<(tot + 255) / 256, 256>>>(bias, out);
}

// round 14
// speedup vs baseline: 1.0439x; 1.0439x over previous
#include <cuda_runtime.h>
#include <cuda_fp16.h>
#include <cstdint>

// Problem constants (fixed by the dataset)
#define PM 4
#define PK 8192
#define PKK (PK/2)            // 4096 packed-k rows
#define PN 28672
#define PG 128                // group size (k elements)
// Geometry: proven R12 config (256 thr, 3 CTAs/SM, 48KB in flight per CTA)
#define THREADS 256
#define COLS_PER_THREAD 4
#define COLS_PER_CTA (THREADS*COLS_PER_THREAD)   // 1024
#define NB (PN/COLS_PER_CTA)                     // 28
#define KSPLIT 16
#define KK_PER_SPLIT (PKK/KSPLIT)                // 256
#define GROUPS_PER_SPLIT (KK_PER_SPLIT/(PG/2))   // 4
// cp.async staging (16KB chunks, 4-stage ring = 64KB)
#define RCH 4                                    // rows per chunk
#define CHUNKS (KK_PER_SPLIT/RCH)                // 64
#define CHUNKS_PER_GROUP ((PG/2)/RCH)            // 16
#define STAGES 4
// Dynamic smem layout
#define WSM_BYTES (STAGES * RCH * COLS_PER_CTA * 4)   // 65536
#define XS_BYTES  (KK_PER_SPLIT * 4 * 8)              // 8192
#define SMEM_TOTAL (WSM_BYTES + XS_BYTES)             // 73728

// Split-K partials: [KSPLIT][M][N] fp32 (7.3MB). Static device global.
__device__ float g_scratch[KSPLIT * PM * PN];

// Packed f32x2 FMA (Blackwell, PTX-only)
__device__ __forceinline__ void fma_f32x2(unsigned long long& acc,
                                          unsigned long long a,
                                          unsigned long long b) {
    asm("fma.rn.f32x2 %0, %1, %2, %0;" : "+l"(acc) : "l"(a), "l"(b));
}
__device__ __forceinline__ unsigned long long pack_f32x2(float lo, float hi) {
    unsigned long long r;
    asm("mov.b64 %0, {%1, %2};" : "=l"(r) : "f"(lo), "f"(hi));
    return r;
}
__device__ __forceinline__ void unpack_f32x2(unsigned long long v, float& lo, float& hi) {
    asm("mov.b64 {%0, %1}, %2;" : "=f"(lo), "=f"(hi) : "l"(v));
}
__device__ __forceinline__ uint32_t smem_u32(const void* p) {
    uint32_t a;
    asm("{ .reg .u64 t; cvta.to.shared.u64 t, %1; cvt.u32.u64 %0, t; }" : "=r"(a) : "l"(p));
    return a;
}
// cp.async with L2 evict_first hint: the weight stream has ZERO reuse, so keep
// it from evicting scratch/x/scales out of L2.
__device__ __forceinline__ void cp_async16_ef(uint32_t dst, const void* src,
                                              unsigned long long pol) {
    asm volatile("cp.async.cg.shared.global.L2::cache_hint [%0], [%1], 16, %2;"
                 :: "r"(dst), "l"(src), "l"(pol) : "memory");
}
__device__ __forceinline__ void cp_commit() {
    asm volatile("cp.async.commit_group;" ::: "memory");
}
template<int N>
__device__ __forceinline__ void cp_wait() {
    asm volatile("cp.async.wait_group %0;" :: "n"(N) : "memory");
}

extern __shared__ char dynsmem[];

__global__ void __launch_bounds__(THREADS, 3)
int4gemv_main(const float* __restrict__ x,      // fp16 promoted to f32 by harness
              const int*   __restrict__ w,
              const float* __restrict__ scales) // fp16 promoted to f32 by harness
{
    // Dynamic smem: [STAGES][RCH][COLS_PER_CTA] ints, then xs2.
    int* wsm = reinterpret_cast<int*>(dynsmem);
    unsigned long long* xs2 = reinterpret_cast<unsigned long long*>(dynsmem + WSM_BYTES);

    const int tid     = threadIdx.x;
    const int nb      = blockIdx.x;
    const int ks      = blockIdx.y;
    const int kk0     = ks * KK_PER_SPLIT;
    const int colBase = nb * COLS_PER_CTA + tid * COLS_PER_THREAD;

    // L2 evict_first policy for the streaming weight loads.
    unsigned long long pol;
    asm("createpolicy.fractional.L2::evict_first.b64 %0, 1.0;" : "=l"(pol));

    // Preload x slice: xs2[kk*4 + m] = (x[m][2kk], x[m][2kk+1]) via float2 loads.
    {
        float2* xsf2 = reinterpret_cast<float2*>(xs2);
        for (int i = tid; i < KK_PER_SPLIT * 4; i += THREADS) {
            const int kkl = i >> 2;
            const int m   = i & 3;
            xsf2[kkl * 4 + m] =
                *reinterpret_cast<const float2*>(x + m * PK + 2 * (kk0 + kkl));
        }
    }
    __syncthreads();   // xs2 is cross-thread; wsm is NOT (self-produced/consumed)

    // Each thread copies, for every row, the 16B it will itself consume.
    const uint32_t wsm_base = smem_u32(wsm) + (uint32_t)tid * 16u;
    const int*     wsrcBase = w + colBase;   // + row*PN per row

    // Issue one chunk (RCH rows x 16B/thread) into a stage. Out-of-range chunks
    // still commit an EMPTY group (legal) so wait_group bookkeeping stays exact.
    auto issue_chunk = [&](int chunk, int stage) {
        if (chunk < CHUNKS) {
            #pragma unroll
            for (int j = 0; j < RCH; ++j) {
                const int row = kk0 + chunk * RCH + j;   // always in-split: no overfetch
                cp_async16_ef(wsm_base + (uint32_t)(stage * RCH + j) * (COLS_PER_CTA * 4),
                              wsrcBase + (size_t)row * PN, pol);
            }
        }
        cp_commit();
    };

    // acc2[c][m] = (sum over even k, sum over odd k) as packed f32x2
    unsigned long long acc2[COLS_PER_THREAD][PM];
    #pragma unroll
    for (int c = 0; c < COLS_PER_THREAD; ++c)
        #pragma unroll
        for (int m = 0; m < PM; ++m) acc2[c][m] = 0ull;

    const __half2 c1032 = __half2half2(__ushort_as_half((unsigned short)0x6408)); // 1032.0h

    // Prologue: fill all 4 stages -> 3 chunks in flight during each compute.
    #pragma unroll
    for (int p = 0; p < STAGES; ++p) issue_chunk(p, p);

    __half2 s2[COLS_PER_THREAD];
    #pragma unroll 4
    for (int i = 0; i < CHUNKS; ++i) {
        const int stage = i & (STAGES - 1);

        // Refresh scales at group boundaries.
        if ((i % CHUNKS_PER_GROUP) == 0) {
            const int grow = ks * GROUPS_PER_SPLIT + (i / CHUNKS_PER_GROUP);
            float4 sv = *reinterpret_cast<const float4*>(scales + (size_t)grow * PN + colBase);
            s2[0] = __half2half2(__float2half_rn(sv.x));
            s2[1] = __half2half2(__float2half_rn(sv.y));
            s2[2] = __half2half2(__float2half_rn(sv.z));
            s2[3] = __half2half2(__float2half_rn(sv.w));
        }

        cp_wait<STAGES - 1>();   // chunk i complete; i+1..i+3 may remain in flight

        // Compute chunk i: RCH kk rows; each thread reads back its own 16B per row.
        #pragma unroll
        for (int j = 0; j < RCH; ++j) {
            const int kkl = i * RCH + j;
            const unsigned long long* xp = &xs2[kkl * 4];
            unsigned long long xm0 = xp[0];
            unsigned long long xm1 = xp[1];
            unsigned long long xm2 = xp[2];
            unsigned long long xm3 = xp[3];

            int4 wv = *reinterpret_cast<const int4*>(
                &wsm[(stage * RCH + j) * COLS_PER_CTA + tid * 4]);
            int wb[4] = {wv.x, wv.y, wv.z, wv.w};
            #pragma unroll
            for (int c = 0; c < 4; ++c) {
                // nibble -> fp16 magic: (0x6400 | nib) = 1024 + nib ; exact -1032 => nib-8
                unsigned int bb = (unsigned int)wb[c];
                unsigned int t = (((bb << 12) | bb) & 0x000F000Fu) | 0x64006400u;
                __half2 h2 = *reinterpret_cast<__half2*>(&t);
                __half2 w2 = __hsub2(h2, c1032);     // exact: (w-8) in fp16
                __half2 dq = __hmul2(w2, s2[c]);     // fp16 round == reference deq
                float d0 = __half2float(__low2half(dq));   // even k
                float d1 = __half2float(__high2half(dq));  // odd  k
                unsigned long long d64 = pack_f32x2(d0, d1);

                fma_f32x2(acc2[c][0], xm0, d64);
                fma_f32x2(acc2[c][1], xm1, d64);
                fma_f32x2(acc2[c][2], xm2, d64);
                fma_f32x2(acc2[c][3], xm3, d64);
            }
        }

        // Refill the stage we just consumed.
        issue_chunk(i + STAGES, stage);
    }

    // Collapse even/odd halves and write split partials (coalesced float4 per row).
    float* sc = g_scratch + (size_t)ks * PM * PN;
    #pragma unroll
    for (int m = 0; m < PM; ++m) {
        float r[4];
        #pragma unroll
        for (int c = 0; c < 4; ++c) {
            float lo, hi;
            unpack_f32x2(acc2[c][m], lo, hi);
            r[c] = lo + hi;
        }
        float4 v = make_float4(r[0], r[1], r[2], r[3]);
        *reinterpret_cast<float4*>(sc + m * PN + colBase) = v;
    }
}

__global__ void __launch_bounds__(256)
int4gemv_reduce(const float* __restrict__ bias,
                float* __restrict__ out)
{
    // One output element per thread: 114,688 threads,
    // 16 independent coalesced 4B loads each (L2-hot if evict_first worked).
    int idx = blockIdx.x * blockDim.x + threadIdx.x;
    if (idx >= PM * PN) return;

    float s = 0.f;
    #pragma unroll
    for (int ks = 0; ks < KSPLIT; ++ks)
        s += g_scratch[ks * PM * PN + idx];

    int n = idx % PN;
    // Match reference exactly: f32 -> fp16 round, fp16 bias add, back to f32.
    __half h = __float2half_rn(s);
    __half b = __float2half_rn(bias[n]);
    out[idx] = __half2float(__hadd(h, b));
}

extern "C" void kernel_launch(void* const* d_in, const int* in_sizes, int n_in,
                              void* d_out, int out_size)
{
    // Bind inputs BY ELEMENT COUNT (dtype-invariant, robust to ordering):
    //   x: 32768, weight_packed: 117440512, scales: 1835008, bias: 28672
    const float* x      = nullptr;
    const int*   w      = nullptr;
    const float* scales = nullptr;
    const float* bias   = nullptr;

    for (int i = 0; i < n_in; ++i) {
        switch (in_sizes[i]) {
            case PM * PK:        x      = (const float*)d_in[i]; break;
            case PKK * PN:       w      = (const int*)  d_in[i]; break;
            case (PK/PG) * PN:   scales = (const float*)d_in[i]; break;
            case PN:             bias   = (const float*)d_in[i]; break;
            default: break; // group_size scalar etc.
        }
    }

    float* out = (float*)d_out;

    // Host-side attribute set (not a stream op; capture-safe, idempotent).
    static bool attr_done = false;
    if (!attr_done) {
        cudaFuncSetAttribute(int4gemv_main,
                             cudaFuncAttributeMaxDynamicSharedMemorySize, SMEM_TOTAL);
        attr_done = true;
    }

    dim3 grid(NB, KSPLIT);
    int4gemv_main<<<grid, THREADS, SMEM_TOTAL>>>(x, w, scales);

    int tot = PM * PN;
    int4gemv_reduce<<<(tot + 255) / 256, 256>>>(bias, out);
}

// round 15
// speedup vs baseline: 1.0709x; 1.0259x over previous
#include <cuda_runtime.h>
#include <cuda_fp16.h>
#include <cstdint>

// Problem constants (fixed by the dataset)
#define PM 4
#define PK 8192
#define PKK (PK/2)            // 4096 packed-k rows
#define PN 28672
#define PG 128                // group size (k elements)
// Geometry: proven R12/R14 config (256 thr, 3 CTAs/SM, 48KB in flight per CTA)
#define THREADS 256
#define COLS_PER_THREAD 4
#define COLS_PER_CTA (THREADS*COLS_PER_THREAD)   // 1024
#define NB (PN/COLS_PER_CTA)                     // 28
#define KSPLIT 16
#define KK_PER_SPLIT (PKK/KSPLIT)                // 256
#define GROUPS_PER_SPLIT (KK_PER_SPLIT/(PG/2))   // 4
// cp.async staging (16KB chunks, 4-stage ring = 64KB)
#define RCH 4                                    // rows per chunk
#define CHUNKS (KK_PER_SPLIT/RCH)                // 64
#define CHUNKS_PER_GROUP ((PG/2)/RCH)            // 16
#define STAGES 4
// Dynamic smem layout
#define WSM_BYTES (STAGES * RCH * COLS_PER_CTA * 4)   // 65536
#define XS_BYTES  (KK_PER_SPLIT * 4 * 8)              // 8192
#define SMEM_TOTAL (WSM_BYTES + XS_BYTES)             // 73728

// Split-K partials: [KSPLIT][M][N] fp32 (7.3MB). Static device global.
__device__ float g_scratch[KSPLIT * PM * PN];

// Packed f32x2 FMA (Blackwell, PTX-only)
__device__ __forceinline__ void fma_f32x2(unsigned long long& acc,
                                          unsigned long long a,
                                          unsigned long long b) {
    asm("fma.rn.f32x2 %0, %1, %2, %0;" : "+l"(acc) : "l"(a), "l"(b));
}
__device__ __forceinline__ unsigned long long pack_f32x2(float lo, float hi) {
    unsigned long long r;
    asm("mov.b64 %0, {%1, %2};" : "=l"(r) : "f"(lo), "f"(hi));
    return r;
}
__device__ __forceinline__ void unpack_f32x2(unsigned long long v, float& lo, float& hi) {
    asm("mov.b64 {%0, %1}, %2;" : "=f"(lo), "=f"(hi) : "l"(v));
}
__device__ __forceinline__ uint32_t smem_u32(const void* p) {
    uint32_t a;
    asm("{ .reg .u64 t; cvta.to.shared.u64 t, %1; cvt.u32.u64 %0, t; }" : "=r"(a) : "l"(p));
    return a;
}
__device__ __forceinline__ void cp_async16_ef(uint32_t dst, const void* src,
                                              unsigned long long pol) {
    asm volatile("cp.async.cg.shared.global.L2::cache_hint [%0], [%1], 16, %2;"
                 :: "r"(dst), "l"(src), "l"(pol) : "memory");
}
__device__ __forceinline__ void cp_commit() {
    asm volatile("cp.async.commit_group;" ::: "memory");
}
template<int N>
__device__ __forceinline__ void cp_wait() {
    asm volatile("cp.async.wait_group %0;" :: "n"(N) : "memory");
}

extern __shared__ char dynsmem[];

__global__ void __launch_bounds__(THREADS, 3)
int4gemv_main(const float* __restrict__ x,      // fp16 promoted to f32 by harness
              const int*   __restrict__ w,
              const float* __restrict__ scales) // fp16 promoted to f32 by harness
{
    // Dynamic smem: [STAGES][RCH][COLS_PER_CTA] ints, then xs2.
    int* wsm = reinterpret_cast<int*>(dynsmem);
    unsigned long long* xs2 = reinterpret_cast<unsigned long long*>(dynsmem + WSM_BYTES);

    const int tid     = threadIdx.x;
    const int nb      = blockIdx.x;
    const int ks      = blockIdx.y;
    const int kk0     = ks * KK_PER_SPLIT;
    const int colBase = nb * COLS_PER_CTA + tid * COLS_PER_THREAD;

    // L2 evict_first policy for the streaming weight loads (kept from R14: small win).
    unsigned long long pol;
    asm("createpolicy.fractional.L2::evict_first.b64 %0, 1.0;" : "=l"(pol));

    // Preload x slice: xs2[kk*4 + m] = (x[m][2kk], x[m][2kk+1]) via float2 loads.
    {
        float2* xsf2 = reinterpret_cast<float2*>(xs2);
        for (int i = tid; i < KK_PER_SPLIT * 4; i += THREADS) {
            const int kkl = i >> 2;
            const int m   = i & 3;
            xsf2[kkl * 4 + m] =
                *reinterpret_cast<const float2*>(x + m * PK + 2 * (kk0 + kkl));
        }
    }
    __syncthreads();   // xs2 is cross-thread; wsm is NOT (self-produced/consumed)

    // Each thread copies, for every row, the 16B it will itself consume.
    const uint32_t wsm_base = smem_u32(wsm) + (uint32_t)tid * 16u;
    const int*     wsrcBase = w + colBase;   // + row*PN per row

    auto issue_chunk = [&](int chunk, int stage) {
        if (chunk < CHUNKS) {
            #pragma unroll
            for (int j = 0; j < RCH; ++j) {
                const int row = kk0 + chunk * RCH + j;   // always in-split: no overfetch
                cp_async16_ef(wsm_base + (uint32_t)(stage * RCH + j) * (COLS_PER_CTA * 4),
                              wsrcBase + (size_t)row * PN, pol);
            }
        }
        cp_commit();
    };

    // acc2[c][m] = (sum over even k, sum over odd k) as packed f32x2
    unsigned long long acc2[COLS_PER_THREAD][PM];
    #pragma unroll
    for (int c = 0; c < COLS_PER_THREAD; ++c)
        #pragma unroll
        for (int m = 0; m < PM; ++m) acc2[c][m] = 0ull;

    const __half2 c1032 = __half2half2(__ushort_as_half((unsigned short)0x6408)); // 1032.0h

    // Prologue: fill all 4 stages -> 3 chunks in flight during each compute.
    #pragma unroll
    for (int p = 0; p < STAGES; ++p) issue_chunk(p, p);

    __half2 s2[COLS_PER_THREAD];
    #pragma unroll 4
    for (int i = 0; i < CHUNKS; ++i) {
        const int stage = i & (STAGES - 1);

        // Refresh scales at group boundaries.
        if ((i % CHUNKS_PER_GROUP) == 0) {
            const int grow = ks * GROUPS_PER_SPLIT + (i / CHUNKS_PER_GROUP);
            float4 sv = *reinterpret_cast<const float4*>(scales + (size_t)grow * PN + colBase);
            s2[0] = __half2half2(__float2half_rn(sv.x));
            s2[1] = __half2half2(__float2half_rn(sv.y));
            s2[2] = __half2half2(__float2half_rn(sv.z));
            s2[3] = __half2half2(__float2half_rn(sv.w));
        }

        cp_wait<STAGES - 1>();   // chunk i complete; i+1..i+3 may remain in flight

        // Compute chunk i: RCH kk rows; each thread reads back its own 16B per row.
        #pragma unroll
        for (int j = 0; j < RCH; ++j) {
            const int kkl = i * RCH + j;
            const unsigned long long* xp = &xs2[kkl * 4];
            unsigned long long xm0 = xp[0];
            unsigned long long xm1 = xp[1];
            unsigned long long xm2 = xp[2];
            unsigned long long xm3 = xp[3];

            int4 wv = *reinterpret_cast<const int4*>(
                &wsm[(stage * RCH + j) * COLS_PER_CTA + tid * 4]);
            int wb[4] = {wv.x, wv.y, wv.z, wv.w};
            #pragma unroll
            for (int c = 0; c < 4; ++c) {
                // nibble -> fp16 magic: (0x6400 | nib) = 1024 + nib ; exact -1032 => nib-8
                unsigned int bb = (unsigned int)wb[c];
                unsigned int t = (((bb << 12) | bb) & 0x000F000Fu) | 0x64006400u;
                __half2 h2 = *reinterpret_cast<__half2*>(&t);
                __half2 w2 = __hsub2(h2, c1032);     // exact: (w-8) in fp16
                __half2 dq = __hmul2(w2, s2[c]);     // fp16 round == reference deq
                float d0 = __half2float(__low2half(dq));   // even k
                float d1 = __half2float(__high2half(dq));  // odd  k
                unsigned long long d64 = pack_f32x2(d0, d1);

                fma_f32x2(acc2[c][0], xm0, d64);
                fma_f32x2(acc2[c][1], xm1, d64);
                fma_f32x2(acc2[c][2], xm2, d64);
                fma_f32x2(acc2[c][3], xm3, d64);
            }
        }

        // Refill the stage we just consumed.
        issue_chunk(i + STAGES, stage);
    }

    // Collapse even/odd halves and write split partials (coalesced float4 per row).
    float* sc = g_scratch + (size_t)ks * PM * PN;
    #pragma unroll
    for (int m = 0; m < PM; ++m) {
        float r[4];
        #pragma unroll
        for (int c = 0; c < 4; ++c) {
            float lo, hi;
            unpack_f32x2(acc2[c][m], lo, hi);
            r[c] = lo + hi;
        }
        float4 v = make_float4(r[0], r[1], r[2], r[3]);
        *reinterpret_cast<float4*>(sc + m * PN + colBase) = v;
    }

    // PDL: this CTA's dependent work is done (stores above are its last ops).
    cudaTriggerProgrammaticLaunchCompletion();
}

__global__ void __launch_bounds__(256)
int4gemv_reduce(const float* __restrict__ bias,
                float* __restrict__ out)
{
    const int idx = blockIdx.x * blockDim.x + threadIdx.x;
    const int n   = idx % PN;

    // Prefetch bias (independent of scratch) BEFORE the dependency sync — this
    // load's latency overlaps the main kernel's tail.
    float bv = (idx < PM * PN) ? bias[n] : 0.f;

    // PDL: wait for the primary (main) grid to complete before touching scratch.
    cudaGridDependencySynchronize();

    if (idx >= PM * PN) return;

    float s = 0.f;
    #pragma unroll
    for (int ks = 0; ks < KSPLIT; ++ks)
        s += g_scratch[ks * PM * PN + idx];

    // Match reference exactly: f32 -> fp16 round, fp16 bias add, back to f32.
    __half h = __float2half_rn(s);
    __half b = __float2half_rn(bv);
    out[idx] = __half2float(__hadd(h, b));
}

extern "C" void kernel_launch(void* const* d_in, const int* in_sizes, int n_in,
                              void* d_out, int out_size)
{
    // Bind inputs BY ELEMENT COUNT (dtype-invariant, robust to ordering):
    //   x: 32768, weight_packed: 117440512, scales: 1835008, bias: 28672
    const float* x      = nullptr;
    const int*   w      = nullptr;
    const float* scales = nullptr;
    const float* bias   = nullptr;

    for (int i = 0; i < n_in; ++i) {
        switch (in_sizes[i]) {
            case PM * PK:        x      = (const float*)d_in[i]; break;
            case PKK * PN:       w      = (const int*)  d_in[i]; break;
            case (PK/PG) * PN:   scales = (const float*)d_in[i]; break;
            case PN:             bias   = (const float*)d_in[i]; break;
            default: break; // group_size scalar etc.
        }
    }

    float* out = (float*)d_out;

    // Host-side attribute set (not a stream op; capture-safe, idempotent).
    static bool attr_done = false;
    if (!attr_done) {
        cudaFuncSetAttribute(int4gemv_main,
                             cudaFuncAttributeMaxDynamicSharedMemorySize, SMEM_TOTAL);
        attr_done = true;
    }

    dim3 grid(NB, KSPLIT);
    int4gemv_main<<<grid, THREADS, SMEM_TOTAL>>>(x, w, scales);

    // Reduce launched with PDL: starts while main drains; blocks at
    // cudaGridDependencySynchronize() until main's grid completes.
    {
        cudaLaunchConfig_t cfg = {};
        cfg.gridDim  = dim3((PM * PN + 255) / 256, 1, 1);
        cfg.blockDim = dim3(256, 1, 1);
        cfg.dynamicSmemBytes = 0;
        cfg.stream = 0;   // same (capture) stream as the main launch

        cudaLaunchAttribute attrs[1];
        attrs[0].id = cudaLaunchAttributeProgrammaticStreamSerialization;
        attrs[0].val.programmaticStreamSerializationAllowed = 1;
        cfg.attrs    = attrs;
        cfg.numAttrs = 1;

        cudaLaunchKernelEx(&cfg, int4gemv_reduce, bias, out);
    }
}